// round 13
// baseline (speedup 1.0000x reference)
#include <cuda_runtime.h>
#include <math.h>

#define NW 4
#define DIM 16
#define NK 81            // 3^4 Pauli strings {I,Z,Y}^4
#define BMAX 131072
#define EPS 1e-5
#define TILE 64          // batch elements per pool block
#define PITCH 148        // padded floats per element in smem
#define EPT 4            // elements per eval thread
#define EVALBLK 128      // eval grid (256 thr): 128*256*4 = 131072

// ---- device globals (no allocations allowed) ----
__device__ float4 d_C[NK];                 // coefficients [k] -> (w0,w1,w2,w3)
__device__ float  d_partial[EVALBLK][8];   // per-eval-block sums / sumsq
__device__ float  d_t[BMAX * 4];           // pooled angles
__device__ int    d_counter;               // grid barrier counter

// ============================================================
// Kernel A: grid = 1 + ceil(B/TILE).
//   Block 0: resets barrier counter, builds W (threads 0-15,
//     fused RZ*RY*RX -> 8 butterfly stages + CNOT permutes),
//     then 8 warps loop over all 324 (k,w) traces.
//   Blocks 1..: smem-staged pooling (coalesced float4 + STS.128),
//     one thread per (element, wire) -> d_t.
// Precompute work hides under the DRAM-bound pooling wave.
// ============================================================
__global__ void __launch_bounds__(256) pool_pre_kernel(const float* __restrict__ x,
                                                       const float* __restrict__ weights,
                                                       int B) {
    __shared__ __align__(16) float xs[TILE * PITCH];   // 37,888 B
    __shared__ float2 W[DIM][DIM];
    int tid = threadIdx.x;

    if (blockIdx.x == 0) {
        // ---------- precompute branch ----------
        if (tid == 0) d_counter = 0;   // reset grid barrier for kernel B

        if (tid < DIM) {
            int j = tid;
            float2 a[DIM];
#pragma unroll
            for (int i = 0; i < DIM; i++) a[i] = make_float2(i == j ? 1.f : 0.f, 0.f);

#pragma unroll
            for (int l = 0; l < 2; l++) {
#pragma unroll
                for (int w = 0; w < NW; w++) {
                    float cx, sx, cy, sy, cz, sz;
                    __sincosf(weights[(l * NW + w) * 3 + 0] * 0.5f, &sx, &cx);
                    __sincosf(weights[(l * NW + w) * 3 + 1] * 0.5f, &sy, &cy);
                    __sincosf(weights[(l * NW + w) * 3 + 2] * 0.5f, &sz, &cz);
                    // U = RZ*RY*RX; u10 = -conj(u01), u11 = conj(u00)
                    float u00r = cz * cy * cx + sz * sy * sx;
                    float u00i = cz * sy * sx - sz * cy * cx;
                    float u01r = -cz * sy * cx - sz * cy * sx;
                    float u01i = -cz * cy * sx + sz * sy * cx;
                    const int st = 1 << (3 - w);
#pragma unroll
                    for (int i = 0; i < DIM; i++) {
                        if (!(i & st)) {
                            float2 a0 = a[i], a1 = a[i | st];
                            float n0r = u00r * a0.x - u00i * a0.y + u01r * a1.x - u01i * a1.y;
                            float n0i = u00r * a0.y + u00i * a0.x + u01r * a1.y + u01i * a1.x;
                            float n1r = -u01r * a0.x - u01i * a0.y + u00r * a1.x + u00i * a1.y;
                            float n1i = -u01r * a0.y + u01i * a0.x + u00r * a1.y - u00i * a1.x;
                            a[i]      = make_float2(n0r, n0i);
                            a[i | st] = make_float2(n1r, n1i);
                        }
                    }
                }
#pragma unroll
                for (int w = 0; w < NW; w++) {
                    const int cm = 1 << (3 - w);
                    const int tm = 1 << (3 - ((w + 1) & 3));
                    float2 b[DIM];
#pragma unroll
                    for (int i = 0; i < DIM; i++) b[i] = a[(i & cm) ? (i ^ tm) : i];
#pragma unroll
                    for (int i = 0; i < DIM; i++) a[i] = b[i];
                }
            }
#pragma unroll
            for (int p = 0; p < DIM; p++) W[p][j] = a[p];
        }
        __syncthreads();

        // 324 (k,w) pairs over 8 warps; trace spread over 32 lanes
        int warp = tid >> 5, lane = tid & 31;
        for (int pair = warp; pair < NK * 4; pair += 8) {
            int k = pair >> 2, w = pair & 3;

            int kd[4];
            { int kk = k; kd[3] = kk % 3; kk /= 3; kd[2] = kk % 3; kk /= 3; kd[1] = kk % 3; kd[0] = kk / 3; }
            int m = 0, nY = 0;
#pragma unroll
            for (int v = 0; v < 4; v++) if (kd[v] == 2) { m |= 1 << (3 - v); nY++; }

            int a_ = lane >> 1;
            int p0 = (lane & 1) << 3;
            int am = a_ ^ m;
            float r = 1.f;
#pragma unroll
            for (int v = 0; v < 4; v++)
                if (kd[v] != 0) r *= 1.f - 2.f * (float)((am >> (3 - v)) & 1);

            float sr = 0.f, si = 0.f;
#pragma unroll
            for (int pp = 0; pp < 8; pp++) {
                int p = p0 + pp;
                float sgn = ((p >> (3 - w)) & 1) ? -1.f : 1.f;
                float2 wa = W[p][a_], wb = W[p][am];
                sr += sgn * (wa.x * wb.x + wa.y * wb.y);
                si += sgn * (wa.x * wb.y - wa.y * wb.x);
            }
            float Tr = r * sr, Ti = r * si;
#pragma unroll
            for (int off = 16; off; off >>= 1) {
                Tr += __shfl_xor_sync(0xffffffffu, Tr, off);
                Ti += __shfl_xor_sync(0xffffffffu, Ti, off);
            }
            if (lane == 0) {
                float re;
                switch (nY & 3) {
                    case 0: re = Tr; break;
                    case 1: re = Ti; break;
                    case 2: re = -Tr; break;
                    default: re = -Ti; break;
                }
                ((float*)d_C)[k * 4 + w] = re * (1.f / 16.f);
            }
        }
        return;
    }

    // ---------- pooling branch ----------
    int base_elem = (blockIdx.x - 1) * TILE;
    int nelem = B - base_elem; if (nelem > TILE) nelem = TILE;
    if (nelem <= 0) return;
    {
        const float4* xg = (const float4*)(x + (size_t)base_elem * 144);
        int n4 = nelem * 36;
        for (int i = tid; i < n4; i += 256) {
            float4 v = xg[i];
            int idx = i * 4;
            int e = idx / 144;
            int off = idx - e * 144;
            *(float4*)(xs + e * PITCH + off) = v;   // STS.128, conflict-free
        }
    }
    __syncthreads();

    int e = tid >> 2;        // local element 0..63
    int w = tid & 3;         // wire
    if (e < nelem) {
        int r0 = (w >> 1) * 6, c0 = (w & 1) * 6;
        const float* xe = &xs[e * PITCH];
        float sum = 0.f;
#pragma unroll
        for (int ri = 0; ri < 6; ri++) {
            const float2* row = (const float2*)(xe + (r0 + ri) * 12 + c0);
            float2 p0 = row[0], p1 = row[1], p2 = row[2];
            sum += p0.x + p0.y + p1.x + p1.y + p2.x + p2.y;
        }
        d_t[(size_t)(base_elem + e) * 4 + w] = sum * (1.f / 36.f);  // coalesced
    }
}

// ============================================================
// Kernel B: fused eval + batchnorm. Single wave (128 blocks),
// grid barrier via counter spin. q stays in registers across
// the barrier; no qbuf roundtrip, no separate normalize launch.
// ============================================================
__global__ void __launch_bounds__(256) eval_norm_kernel(float* __restrict__ out,
                                                        const float* __restrict__ gamma,
                                                        const float* __restrict__ beta,
                                                        int B, int NT) {
    __shared__ float4 Csh[NK];
    __shared__ float red[8][8];
    __shared__ double sred[256];
    __shared__ float sc_sh[4], sh_sh[4];
    int tid = threadIdx.x;
    int lane = tid & 31, warp = tid >> 5;
    for (int i = tid; i < NK; i += 256) Csh[i] = d_C[i];
    __syncthreads();

    int gid = blockIdx.x * 256 + tid;

    float gc[EPT][4], gs[EPT][4];
    int   eidx[EPT];
    bool  val[EPT];
#pragma unroll
    for (int j = 0; j < EPT; j++) {
        int e = gid + j * NT;
        eidx[j] = e;
        val[j] = (e < B);
        float4 tv = val[j] ? ((const float4*)d_t)[e] : make_float4(0.f, 0.f, 0.f, 0.f);
        __sincosf(tv.x, &gs[j][0], &gc[j][0]);
        __sincosf(tv.y, &gs[j][1], &gc[j][1]);
        __sincosf(tv.z, &gs[j][2], &gc[j][2]);
        __sincosf(tv.w, &gs[j][3], &gc[j][3]);
    }

    float acc[EPT][4];
#pragma unroll
    for (int j = 0; j < EPT; j++)
#pragma unroll
        for (int w = 0; w < 4; w++) acc[j][w] = 0.f;

#pragma unroll
    for (int k0 = 0; k0 < 3; k0++) {
        float a0[EPT];
#pragma unroll
        for (int j = 0; j < EPT; j++)
            a0[j] = (k0 == 0) ? 1.f : (k0 == 1) ? gc[j][0] : -gs[j][0];
#pragma unroll
        for (int k1 = 0; k1 < 3; k1++) {
            float a1[EPT];
#pragma unroll
            for (int j = 0; j < EPT; j++)
                a1[j] = (k1 == 0) ? a0[j] : (k1 == 1) ? a0[j] * gc[j][1] : -a0[j] * gs[j][1];
#pragma unroll
            for (int k2 = 0; k2 < 3; k2++) {
                float a2[EPT];
#pragma unroll
                for (int j = 0; j < EPT; j++)
                    a2[j] = (k2 == 0) ? a1[j] : (k2 == 1) ? a1[j] * gc[j][2] : -a1[j] * gs[j][2];
#pragma unroll
                for (int k3 = 0; k3 < 3; k3++) {
                    float4 cc = Csh[((k0 * 3 + k1) * 3 + k2) * 3 + k3];
#pragma unroll
                    for (int j = 0; j < EPT; j++) {
                        float a3 = (k3 == 0) ? a2[j] : (k3 == 1) ? a2[j] * gc[j][3] : -a2[j] * gs[j][3];
                        acc[j][0] = fmaf(cc.x, a3, acc[j][0]);
                        acc[j][1] = fmaf(cc.y, a3, acc[j][1]);
                        acc[j][2] = fmaf(cc.z, a3, acc[j][2]);
                        acc[j][3] = fmaf(cc.w, a3, acc[j][3]);
                    }
                }
            }
        }
    }

    // per-block partial stats
    float v[8] = {0.f, 0.f, 0.f, 0.f, 0.f, 0.f, 0.f, 0.f};
#pragma unroll
    for (int j = 0; j < EPT; j++) {
        if (val[j]) {
#pragma unroll
            for (int w = 0; w < 4; w++) {
                v[w]     += acc[j][w];
                v[4 + w] += acc[j][w] * acc[j][w];
            }
        }
    }
#pragma unroll
    for (int off = 16; off; off >>= 1)
#pragma unroll
        for (int i = 0; i < 8; i++) v[i] += __shfl_xor_sync(0xffffffffu, v[i], off);
    if (lane == 0) {
#pragma unroll
        for (int i = 0; i < 8; i++) red[i][warp] = v[i];
    }
    __syncthreads();
    if (tid < 8) {
        float t = 0.f;
#pragma unroll
        for (int wp = 0; wp < 8; wp++) t += red[tid][wp];
        d_partial[blockIdx.x][tid] = t;
    }

    // ---- grid-wide barrier (single co-resident wave guaranteed) ----
    __threadfence();
    __syncthreads();
    if (tid == 0) {
        atomicAdd(&d_counter, 1);
        while (*((volatile int*)&d_counter) < EVALBLK) { }
    }
    __syncthreads();
    __threadfence();

    // every block redundantly reduces the 128x8 partials (L2-hot)
    {
        int stat = tid & 7, grp = tid >> 3;   // 32 groups
        double a = 0.0;
        for (int j = grp; j < EVALBLK; j += 32) a += (double)d_partial[j][stat];
        sred[tid] = a;
    }
    __syncthreads();
#pragma unroll
    for (int off = 128; off >= 8; off >>= 1) {
        if (tid < off) sred[tid] += sred[tid + off];
        __syncthreads();
    }
    if (tid < 4) {
        double mean = sred[tid] / (double)B;
        double var  = sred[tid + 4] / (double)B - mean * mean;
        double sc = (double)gamma[tid] / sqrt(var + (double)EPS);
        double sh = (double)beta[tid] - mean * sc;
        sc_sh[tid] = (float)sc;
        sh_sh[tid] = (float)sh;
    }
    __syncthreads();

    float4 sc = make_float4(sc_sh[0], sc_sh[1], sc_sh[2], sc_sh[3]);
    float4 sh = make_float4(sh_sh[0], sh_sh[1], sh_sh[2], sh_sh[3]);

    // write normalized output straight from registers (coalesced float4)
#pragma unroll
    for (int j = 0; j < EPT; j++) {
        if (val[j]) {
            ((float4*)out)[eidx[j]] = make_float4(fmaf(acc[j][0], sc.x, sh.x),
                                                  fmaf(acc[j][1], sc.y, sh.y),
                                                  fmaf(acc[j][2], sc.z, sh.z),
                                                  fmaf(acc[j][3], sc.w, sh.w));
        }
    }
}

extern "C" void kernel_launch(void* const* d_in, const int* in_sizes, int n_in,
                              void* d_out, int out_size) {
    const float* x       = (const float*)d_in[0];
    const float* weights = (const float*)d_in[1];
    const float* gamma   = (const float*)d_in[2];
    const float* beta    = (const float*)d_in[3];
    int B = in_sizes[0] / 144;
    if (B > BMAX) B = BMAX;

    int pblocks = 1 + (B + TILE - 1) / TILE;       // 2049: block 0 = precompute
    pool_pre_kernel<<<pblocks, 256>>>(x, weights, B);

    int NT = EVALBLK * 256;                        // 32768 threads, 4 elems each
    eval_norm_kernel<<<EVALBLK, 256>>>((float*)d_out, gamma, beta, B, NT);
}